// round 1
// baseline (speedup 1.0000x reference)
#include <cuda_runtime.h>
#include <cstdint>

// ============================================================================
// ECGRGNN: GRU(scalar-input, H=64) over 6144 nodes x 500 steps, then
// (algebraically collapsed) GCN head:
//   out[g] = relu(relu(mean_l h[g,l] @ W1 + b1) @ W2 + b2) @ Wfc + bfc
// The complete-graph structure makes every GCN layer output identical across
// the 12 leads of a graph (deg+1 == 12, norm == 1/12 for every edge), so the
// two GCN layers + mean-pool reduce to dense 512-row matmuls on the per-graph
// mean of h.
// ============================================================================

#define T_LEN 500
#define N_NODES 6144
#define NCTA 148
#define WARPS_PER_CTA 16
#define CTA_THREADS 512
#define TOT_WARPS (NCTA * WARPS_PER_CTA)   // 2368; nodes/warp = 6144/2368 = 96/37
#define SMEM_W_U64 6144                    // 3*64*32 float2 pairs = 6144 u64 = 48KB
#define MAX_NODES_CTA 42
#define SMEM_BYTES (SMEM_W_U64 * 8 + MAX_NODES_CTA * 128 * 8)  // 49152 + 43008 = 92160

typedef unsigned long long u64;

__device__ float g_h[N_NODES * 64];  // GRU outputs (scratch between kernels)

// ---------------- packed f32x2 + fast-math helpers ----------------

__device__ __forceinline__ u64 pk(float lo, float hi) {
    u64 r;
    asm("mov.b64 %0, {%1, %2};" : "=l"(r) : "f"(lo), "f"(hi));
    return r;
}
__device__ __forceinline__ void upk(u64 v, float& lo, float& hi) {
    asm("mov.b64 {%0, %1}, %2;" : "=f"(lo), "=f"(hi) : "l"(v));
}
__device__ __forceinline__ u64 fma2(u64 a, u64 b, u64 c) {
    u64 d;
    asm("fma.rn.f32x2 %0, %1, %2, %3;" : "=l"(d) : "l"(a), "l"(b), "l"(c));
    return d;
}
__device__ __forceinline__ float ex2a(float x) {
    float r;
    asm("ex2.approx.f32 %0, %1;" : "=f"(r) : "f"(x));
    return r;
}
__device__ __forceinline__ float rcpa(float x) {
    float r;
    asm("rcp.approx.f32 %0, %1;" : "=f"(r) : "f"(x));
    return r;
}
// sigmoid(v) = 1 / (1 + e^-v);  e^-v = 2^(-v*log2 e)
__device__ __forceinline__ float sigm(float v) {
    return rcpa(1.0f + ex2a(v * -1.4426950408889634f));
}
// tanh(v) = 2 / (1 + e^-2v) - 1
__device__ __forceinline__ float tanh_fast(float v) {
    return fmaf(2.0f, rcpa(1.0f + ex2a(v * -2.8853900817779268f)), -1.0f);
}

// ---------------- GRU per-warp body (NB = nodes handled by this warp) -------
//
// Lane l owns hidden units j = l and j+32 for each of its NB nodes.
// Gate rows for hidden j: r -> j, z -> 64+j, n -> 128+j.
// SMEM weights wb: ulonglong2 per (gate g, k-pair k2, lane l):
//   .x = ( w_hh[g*64+l][2k2],   w_hh[g*64+32+l][2k2]   )   packed f32x2
//   .y = ( w_hh[g*64+l][2k2+1], w_hh[g*64+32+l][2k2+1] )
// SMEM h (per node, ping-pong): u64[k] = (h[k], h[k]) duplicated so it is the
// FFMA2 B-operand directly (broadcast LDS.128, conflict-free).

template <int NB>
__device__ __forceinline__ void gru_run(
    const float* __restrict__ x_raw,
    const float* __restrict__ w_ih,
    const float* __restrict__ b_ih,
    const float* __restrict__ b_hh,
    const ulonglong2* __restrict__ wb,
    u64* hbase0,   // hsm + (local node 0)*128
    int n0, int lane)
{
    // per-lane packed constants
    const u64 win0 = pk(w_ih[lane],       w_ih[32 + lane]);
    const u64 win1 = pk(w_ih[64 + lane],  w_ih[96 + lane]);
    const u64 win2 = pk(w_ih[128 + lane], w_ih[160 + lane]);
    const u64 bb0  = pk(b_ih[lane] + b_hh[lane],           b_ih[32 + lane] + b_hh[32 + lane]);
    const u64 bb1  = pk(b_ih[64 + lane] + b_hh[64 + lane], b_ih[96 + lane] + b_hh[96 + lane]);
    const u64 bhh2 = pk(b_hh[128 + lane], b_hh[160 + lane]);
    const u64 bih2 = pk(b_ih[128 + lane], b_ih[160 + lane]);

    float hlo[NB], hhi[NB], xr[NB];
#pragma unroll
    for (int j = 0; j < NB; j++) { hlo[j] = 0.0f; hhi[j] = 0.0f; xr[j] = 0.0f; }

    for (int t = 0; t < T_LEN; t++) {
        if ((t & 31) == 0) {
            int tt = t + lane;
#pragma unroll
            for (int j = 0; j < NB; j++)
                xr[j] = (tt < T_LEN) ? x_raw[(size_t)(n0 + j) * T_LEN + tt] : 0.0f;
        }

        // ---- matvec: gh[g][j] accumulators (bias folded in) ----
        u64 a0[NB], a1[NB], a2[NB];
#pragma unroll
        for (int j = 0; j < NB; j++) { a0[j] = bb0; a1[j] = bb1; a2[j] = bhh2; }

        const u64* hrd[NB];
#pragma unroll
        for (int j = 0; j < NB; j++) hrd[j] = hbase0 + j * 128 + (t & 1) * 64;

#pragma unroll
        for (int k2 = 0; k2 < 32; k2++) {
            ulonglong2 w0 = wb[k2 * 32 + lane];
            ulonglong2 w1 = wb[1024 + k2 * 32 + lane];
            ulonglong2 w2 = wb[2048 + k2 * 32 + lane];
#pragma unroll
            for (int j = 0; j < NB; j++) {
                ulonglong2 hv = *(const ulonglong2*)(hrd[j] + 2 * k2);
                a0[j] = fma2(w0.x, hv.x, a0[j]);
                a0[j] = fma2(w0.y, hv.y, a0[j]);
                a1[j] = fma2(w1.x, hv.x, a1[j]);
                a1[j] = fma2(w1.y, hv.y, a1[j]);
                a2[j] = fma2(w2.x, hv.x, a2[j]);
                a2[j] = fma2(w2.y, hv.y, a2[j]);
            }
        }

        // ---- gates + state update ----
        int sel = t & 31;
#pragma unroll
        for (int j = 0; j < NB; j++) {
            float xv = __shfl_sync(0xffffffffu, xr[j], sel);
            u64 xp = pk(xv, xv);
            u64 sr  = fma2(xp, win0, a0[j]);          // ir + hr (biases folded)
            u64 sz  = fma2(xp, win1, a1[j]);          // iz + hz
            u64 gin = fma2(xp, win2, bih2);           // ig
            float srl, srh, szl, szh;
            upk(sr, srl, srh);
            upk(sz, szl, szh);
            float rl = sigm(srl), rh = sigm(srh);
            float zl = sigm(szl), zh = sigm(szh);
            u64 sn = fma2(pk(rl, rh), a2[j], gin);    // ig + r*hg
            float snl, snh;
            upk(sn, snl, snh);
            float nlv = tanh_fast(snl);
            float nhv = tanh_fast(snh);
            float nh_lo = fmaf(zl, hlo[j] - nlv, nlv);  // (1-z)n + z h
            float nh_hi = fmaf(zh, hhi[j] - nhv, nhv);
            hlo[j] = nh_lo;
            hhi[j] = nh_hi;
            u64* hw = hbase0 + j * 128 + ((t + 1) & 1) * 64;
            hw[lane]      = pk(nh_lo, nh_lo);
            hw[lane + 32] = pk(nh_hi, nh_hi);
        }
        __syncwarp();
    }

#pragma unroll
    for (int j = 0; j < NB; j++) {
        g_h[(size_t)(n0 + j) * 64 + lane]      = hlo[j];
        g_h[(size_t)(n0 + j) * 64 + lane + 32] = hhi[j];
    }
}

// ---------------- GRU kernel ----------------

__global__ void __launch_bounds__(CTA_THREADS, 1)
gru_kernel(const float* __restrict__ x_raw,
           const float* __restrict__ w_ih,
           const float* __restrict__ w_hh,
           const float* __restrict__ b_ih,
           const float* __restrict__ b_hh)
{
    extern __shared__ u64 smem[];
    ulonglong2* wb = (ulonglong2*)smem;          // 3072 ulonglong2 = 48KB
    u64* hsm = smem + SMEM_W_U64;                // per-node ping-pong dup-h

    int tid = threadIdx.x;

    // stage w_hh into the lane-paired, k-paired layout
    for (int i = tid; i < 3072; i += CTA_THREADS) {
        int g = i >> 10, rem = i & 1023, k2 = rem >> 5, l = rem & 31;
        int r0 = g * 64 + l, r1 = r0 + 32, k = k2 * 2;
        ulonglong2 v;
        v.x = pk(w_hh[r0 * 64 + k],     w_hh[r1 * 64 + k]);
        v.y = pk(w_hh[r0 * 64 + k + 1], w_hh[r1 * 64 + k + 1]);
        wb[i] = v;
    }

    int cta_w0 = blockIdx.x * WARPS_PER_CTA;
    int cta_n0 = (cta_w0 * 96) / 37;
    int cta_n1 = ((cta_w0 + WARPS_PER_CTA) * 96) / 37;
    int cta_cnt = cta_n1 - cta_n0;
    for (int i = tid; i < cta_cnt * 128; i += CTA_THREADS) hsm[i] = 0ULL;
    __syncthreads();

    int wid = tid >> 5, lane = tid & 31;
    int gw = cta_w0 + wid;                 // global warp id, 0..2367
    int n0 = (gw * 96) / 37;               // balanced node partition (exact: 2368*96/37 = 6144)
    int n1 = ((gw + 1) * 96) / 37;
    u64* hbase0 = hsm + (n0 - cta_n0) * 128;

    if (n1 - n0 == 3)
        gru_run<3>(x_raw, w_ih, b_ih, b_hh, wb, hbase0, n0, lane);
    else
        gru_run<2>(x_raw, w_ih, b_ih, b_hh, wb, hbase0, n0, lane);
}

// ---------------- collapsed GCN head ----------------
// out[g] = relu(relu(hbar @ W1 + b1) @ W2 + b2) @ Wfc + bfc,  hbar = mean_12 h

__global__ void __launch_bounds__(128)
head_kernel(const float* __restrict__ W1, const float* __restrict__ b1,
            const float* __restrict__ W2, const float* __restrict__ b2,
            const float* __restrict__ Wfc, const float* __restrict__ bfc,
            float* __restrict__ out)
{
    __shared__ float hbar[64];
    __shared__ float x1s[128];
    __shared__ float x2s[128];
    int g = blockIdx.x, tid = threadIdx.x;

    if (tid < 64) {
        float s = 0.0f;
#pragma unroll
        for (int l = 0; l < 12; l++)
            s += g_h[(size_t)(g * 12 + l) * 64 + tid];
        hbar[tid] = s * (1.0f / 12.0f);
    }
    __syncthreads();

    float s = b1[tid];
#pragma unroll
    for (int k = 0; k < 64; k++)
        s = fmaf(hbar[k], W1[k * 128 + tid], s);
    x1s[tid] = fmaxf(s, 0.0f);
    __syncthreads();

    float s2 = b2[tid];
#pragma unroll
    for (int k = 0; k < 128; k++)
        s2 = fmaf(x1s[k], W2[k * 128 + tid], s2);
    x2s[tid] = fmaxf(s2, 0.0f);
    __syncthreads();

    if (tid < 5) {
        float o = bfc[tid];
#pragma unroll
        for (int k = 0; k < 128; k++)
            o = fmaf(x2s[k], Wfc[k * 5 + tid], o);
        out[g * 5 + tid] = o;
    }
}

// ---------------- launch ----------------
// metadata order: 0 x_raw, 1 edge_index, 2 batch, 3 w_ih, 4 w_hh, 5 b_ih,
//                 6 b_hh, 7 W1, 8 b1, 9 W2, 10 b2, 11 Wfc, 12 bfc

extern "C" void kernel_launch(void* const* d_in, const int* in_sizes, int n_in,
                              void* d_out, int out_size)
{
    const float* x_raw = (const float*)d_in[0];
    const float* w_ih  = (const float*)d_in[3];
    const float* w_hh  = (const float*)d_in[4];
    const float* b_ih  = (const float*)d_in[5];
    const float* b_hh  = (const float*)d_in[6];
    const float* W1    = (const float*)d_in[7];
    const float* b1    = (const float*)d_in[8];
    const float* W2    = (const float*)d_in[9];
    const float* b2    = (const float*)d_in[10];
    const float* Wfc   = (const float*)d_in[11];
    const float* bfc   = (const float*)d_in[12];
    float* out = (float*)d_out;

    cudaFuncSetAttribute(gru_kernel, cudaFuncAttributeMaxDynamicSharedMemorySize, SMEM_BYTES);

    gru_kernel<<<NCTA, CTA_THREADS, SMEM_BYTES>>>(x_raw, w_ih, w_hh, b_ih, b_hh);
    head_kernel<<<512, 128>>>(W1, b1, W2, b2, Wfc, bfc, out);
}

// round 2
// speedup vs baseline: 1.0368x; 1.0368x over previous
#include <cuda_runtime.h>
#include <cstdint>

// ============================================================================
// ECGRGNN: GRU(scalar-input, H=64) over 6144 nodes x 500 steps, then
// (algebraically collapsed) GCN head:
//   out[g] = relu(relu(mean_l h[g,l] @ W1 + b1) @ W2 + b2) @ Wfc + bfc
//
// R2: SMEM-crossbar analysis showed R1 was bound by per-warp re-reads of the
// 48KB packed w_hh (16 warps/CTA x 96 LDS.128/step). Now 4 warps/CTA
// (1 per SMSP), each warp carries 10-11 nodes, so the weight read is
// amortized 4x and the FMA pipe becomes the binding resource.
// ============================================================================

#define T_LEN 500
#define N_NODES 6144
#define NCTA 148
#define WARPS_PER_CTA 4
#define CTA_THREADS 128
#define TOT_WARPS (NCTA * WARPS_PER_CTA)   // 592; nodes/warp = 6144/592 = 384/37
#define SMEM_W_U64 6144                    // 3*64*32 float2 pairs = 6144 u64 = 48KB
#define MAX_NODES_CTA 44
#define SMEM_BYTES (SMEM_W_U64 * 8 + MAX_NODES_CTA * 128 * 8)  // 49152 + 45056 = 94208

typedef unsigned long long u64;

__device__ float g_h[N_NODES * 64];  // GRU outputs (scratch between kernels)

// ---------------- packed f32x2 + fast-math helpers ----------------

__device__ __forceinline__ u64 pk(float lo, float hi) {
    u64 r;
    asm("mov.b64 %0, {%1, %2};" : "=l"(r) : "f"(lo), "f"(hi));
    return r;
}
__device__ __forceinline__ void upk(u64 v, float& lo, float& hi) {
    asm("mov.b64 {%0, %1}, %2;" : "=f"(lo), "=f"(hi) : "l"(v));
}
__device__ __forceinline__ u64 fma2(u64 a, u64 b, u64 c) {
    u64 d;
    asm("fma.rn.f32x2 %0, %1, %2, %3;" : "=l"(d) : "l"(a), "l"(b), "l"(c));
    return d;
}
__device__ __forceinline__ float ex2a(float x) {
    float r;
    asm("ex2.approx.f32 %0, %1;" : "=f"(r) : "f"(x));
    return r;
}
__device__ __forceinline__ float rcpa(float x) {
    float r;
    asm("rcp.approx.f32 %0, %1;" : "=f"(r) : "f"(x));
    return r;
}
// sigmoid(v) = 1 / (1 + e^-v)
__device__ __forceinline__ float sigm(float v) {
    return rcpa(1.0f + ex2a(v * -1.4426950408889634f));
}
// tanh(v) = 2 / (1 + e^-2v) - 1
__device__ __forceinline__ float tanh_fast(float v) {
    return fmaf(2.0f, rcpa(1.0f + ex2a(v * -2.8853900817779268f)), -1.0f);
}

// ---------------- GRU per-warp body (NB = nodes handled by this warp) -------
//
// Lane l owns hidden units j = l and j+32 for each of its NB nodes.
// Gate rows for hidden j: r -> j, z -> 64+j, n -> 128+j.
// SMEM weights wb: ulonglong2 per (gate g, k-pair k2, lane l):
//   .x = ( w_hh[g*64+l][2k2],   w_hh[g*64+32+l][2k2]   )   packed f32x2
//   .y = ( w_hh[g*64+l][2k2+1], w_hh[g*64+32+l][2k2+1] )
// SMEM h (per node, ping-pong): u64[k] = (h[k], h[k]) duplicated so it is the
// FFMA2 B-operand directly (broadcast LDS.128, conflict-free, crossbar ~1cyc).

template <int NB>
__device__ __forceinline__ void gru_run(
    const float* __restrict__ x_raw,
    const float* __restrict__ w_ih,
    const float* __restrict__ b_ih,
    const float* __restrict__ b_hh,
    const ulonglong2* __restrict__ wb,
    u64* hbase0,   // hsm + (local node 0)*128
    int n0, int lane)
{
    // per-lane packed constants
    const u64 win0 = pk(w_ih[lane],       w_ih[32 + lane]);
    const u64 win1 = pk(w_ih[64 + lane],  w_ih[96 + lane]);
    const u64 win2 = pk(w_ih[128 + lane], w_ih[160 + lane]);
    const u64 bb0  = pk(b_ih[lane] + b_hh[lane],           b_ih[32 + lane] + b_hh[32 + lane]);
    const u64 bb1  = pk(b_ih[64 + lane] + b_hh[64 + lane], b_ih[96 + lane] + b_hh[96 + lane]);
    const u64 bhh2 = pk(b_hh[128 + lane], b_hh[160 + lane]);
    const u64 bih2 = pk(b_ih[128 + lane], b_ih[160 + lane]);

    float hlo[NB], hhi[NB], xr[NB];
#pragma unroll
    for (int j = 0; j < NB; j++) { hlo[j] = 0.0f; hhi[j] = 0.0f; xr[j] = 0.0f; }

    for (int t = 0; t < T_LEN; t++) {
        if ((t & 31) == 0) {
            int tt = t + lane;
#pragma unroll
            for (int j = 0; j < NB; j++)
                xr[j] = (tt < T_LEN) ? x_raw[(size_t)(n0 + j) * T_LEN + tt] : 0.0f;
        }

        // ---- matvec: gh[g][j] accumulators (bias folded in) ----
        u64 a0[NB], a1[NB], a2[NB];
#pragma unroll
        for (int j = 0; j < NB; j++) { a0[j] = bb0; a1[j] = bb1; a2[j] = bhh2; }

        const u64* hb = hbase0 + (t & 1) * 64;   // base + imm offsets below

#pragma unroll 8
        for (int k2 = 0; k2 < 32; k2++) {
            ulonglong2 w0 = wb[k2 * 32 + lane];
            ulonglong2 w1 = wb[1024 + k2 * 32 + lane];
            ulonglong2 w2 = wb[2048 + k2 * 32 + lane];
#pragma unroll
            for (int j = 0; j < NB; j++) {
                ulonglong2 hv = *(const ulonglong2*)(hb + j * 128 + 2 * k2);
                a0[j] = fma2(w0.x, hv.x, a0[j]);
                a0[j] = fma2(w0.y, hv.y, a0[j]);
                a1[j] = fma2(w1.x, hv.x, a1[j]);
                a1[j] = fma2(w1.y, hv.y, a1[j]);
                a2[j] = fma2(w2.x, hv.x, a2[j]);
                a2[j] = fma2(w2.y, hv.y, a2[j]);
            }
        }

        // ---- gates + state update ----
        int sel = t & 31;
        u64* hw = hbase0 + ((t + 1) & 1) * 64;
#pragma unroll
        for (int j = 0; j < NB; j++) {
            float xv = __shfl_sync(0xffffffffu, xr[j], sel);
            u64 xp = pk(xv, xv);
            u64 sr  = fma2(xp, win0, a0[j]);          // ir + hr (biases folded)
            u64 sz  = fma2(xp, win1, a1[j]);          // iz + hz
            u64 gin = fma2(xp, win2, bih2);           // ig
            float srl, srh, szl, szh;
            upk(sr, srl, srh);
            upk(sz, szl, szh);
            float rl = sigm(srl), rh = sigm(srh);
            float zl = sigm(szl), zh = sigm(szh);
            u64 sn = fma2(pk(rl, rh), a2[j], gin);    // ig + r*hg
            float snl, snh;
            upk(sn, snl, snh);
            float nlv = tanh_fast(snl);
            float nhv = tanh_fast(snh);
            float nh_lo = fmaf(zl, hlo[j] - nlv, nlv);  // (1-z)n + z h
            float nh_hi = fmaf(zh, hhi[j] - nhv, nhv);
            hlo[j] = nh_lo;
            hhi[j] = nh_hi;
            hw[j * 128 + lane]      = pk(nh_lo, nh_lo);
            hw[j * 128 + lane + 32] = pk(nh_hi, nh_hi);
        }
        __syncwarp();
    }

#pragma unroll
    for (int j = 0; j < NB; j++) {
        g_h[(size_t)(n0 + j) * 64 + lane]      = hlo[j];
        g_h[(size_t)(n0 + j) * 64 + lane + 32] = hhi[j];
    }
}

// ---------------- GRU kernel ----------------

__global__ void __launch_bounds__(CTA_THREADS, 1)
gru_kernel(const float* __restrict__ x_raw,
           const float* __restrict__ w_ih,
           const float* __restrict__ w_hh,
           const float* __restrict__ b_ih,
           const float* __restrict__ b_hh)
{
    extern __shared__ u64 smem[];
    ulonglong2* wb = (ulonglong2*)smem;          // 3072 ulonglong2 = 48KB
    u64* hsm = smem + SMEM_W_U64;                // per-node ping-pong dup-h

    int tid = threadIdx.x;

    // stage w_hh into the lane-paired, k-paired layout
    for (int i = tid; i < 3072; i += CTA_THREADS) {
        int g = i >> 10, rem = i & 1023, k2 = rem >> 5, l = rem & 31;
        int r0 = g * 64 + l, r1 = r0 + 32, k = k2 * 2;
        ulonglong2 v;
        v.x = pk(w_hh[r0 * 64 + k],     w_hh[r1 * 64 + k]);
        v.y = pk(w_hh[r0 * 64 + k + 1], w_hh[r1 * 64 + k + 1]);
        wb[i] = v;
    }

    int cta_w0 = blockIdx.x * WARPS_PER_CTA;
    int cta_n0 = (cta_w0 * 384) / 37;
    int cta_n1 = ((cta_w0 + WARPS_PER_CTA) * 384) / 37;
    int cta_cnt = cta_n1 - cta_n0;
    for (int i = tid; i < cta_cnt * 128; i += CTA_THREADS) hsm[i] = 0ULL;
    __syncthreads();

    int wid = tid >> 5, lane = tid & 31;
    int gw = cta_w0 + wid;                 // global warp id, 0..591
    int n0 = (gw * 384) / 37;              // balanced node partition (592*384/37 = 6144)
    int n1 = ((gw + 1) * 384) / 37;
    u64* hbase0 = hsm + (n0 - cta_n0) * 128;

    if (n1 - n0 == 11)
        gru_run<11>(x_raw, w_ih, b_ih, b_hh, wb, hbase0, n0, lane);
    else
        gru_run<10>(x_raw, w_ih, b_ih, b_hh, wb, hbase0, n0, lane);
}

// ---------------- collapsed GCN head ----------------
// out[g] = relu(relu(hbar @ W1 + b1) @ W2 + b2) @ Wfc + bfc,  hbar = mean_12 h

__global__ void __launch_bounds__(128)
head_kernel(const float* __restrict__ W1, const float* __restrict__ b1,
            const float* __restrict__ W2, const float* __restrict__ b2,
            const float* __restrict__ Wfc, const float* __restrict__ bfc,
            float* __restrict__ out)
{
    __shared__ float hbar[64];
    __shared__ float x1s[128];
    __shared__ float x2s[128];
    int g = blockIdx.x, tid = threadIdx.x;

    if (tid < 64) {
        float s = 0.0f;
#pragma unroll
        for (int l = 0; l < 12; l++)
            s += g_h[(size_t)(g * 12 + l) * 64 + tid];
        hbar[tid] = s * (1.0f / 12.0f);
    }
    __syncthreads();

    float s = b1[tid];
#pragma unroll
    for (int k = 0; k < 64; k++)
        s = fmaf(hbar[k], W1[k * 128 + tid], s);
    x1s[tid] = fmaxf(s, 0.0f);
    __syncthreads();

    float s2 = b2[tid];
#pragma unroll
    for (int k = 0; k < 128; k++)
        s2 = fmaf(x1s[k], W2[k * 128 + tid], s2);
    x2s[tid] = fmaxf(s2, 0.0f);
    __syncthreads();

    if (tid < 5) {
        float o = bfc[tid];
#pragma unroll
        for (int k = 0; k < 128; k++)
            o = fmaf(x2s[k], Wfc[k * 5 + tid], o);
        out[g * 5 + tid] = o;
    }
}

// ---------------- launch ----------------
// metadata order: 0 x_raw, 1 edge_index, 2 batch, 3 w_ih, 4 w_hh, 5 b_ih,
//                 6 b_hh, 7 W1, 8 b1, 9 W2, 10 b2, 11 Wfc, 12 bfc

extern "C" void kernel_launch(void* const* d_in, const int* in_sizes, int n_in,
                              void* d_out, int out_size)
{
    const float* x_raw = (const float*)d_in[0];
    const float* w_ih  = (const float*)d_in[3];
    const float* w_hh  = (const float*)d_in[4];
    const float* b_ih  = (const float*)d_in[5];
    const float* b_hh  = (const float*)d_in[6];
    const float* W1    = (const float*)d_in[7];
    const float* b1    = (const float*)d_in[8];
    const float* W2    = (const float*)d_in[9];
    const float* b2    = (const float*)d_in[10];
    const float* Wfc   = (const float*)d_in[11];
    const float* bfc   = (const float*)d_in[12];
    float* out = (float*)d_out;

    cudaFuncSetAttribute(gru_kernel, cudaFuncAttributeMaxDynamicSharedMemorySize, SMEM_BYTES);

    gru_kernel<<<NCTA, CTA_THREADS, SMEM_BYTES>>>(x_raw, w_ih, w_hh, b_ih, b_hh);
    head_kernel<<<512, 128>>>(W1, b1, W2, b2, Wfc, bfc, out);
}

// round 4
// speedup vs baseline: 2.5271x; 2.4373x over previous
#include <cuda_runtime.h>
#include <cuda_fp16.h>
#include <cstdint>

// ============================================================================
// ECGRGNN via warp-level mma.sync (base sm_100 compatible; tcgen05 is not
// available through this toolchain — PTX target is compute_100).
//
// GRU matvec per step: D[192 gates, 48 nodes] = W_hh[192,64] @ h[48,64]^T
// done as m16n8k16 fp16 mma with a 3-term precision split:
//   D = Whi*hhi + Wlo*hhi + Whi*hlo   (fp32 accum; dropped lo*lo ~ 2^-22)
// A = W (row-major, fragments PRELOADED into registers, step-invariant).
// B = h (ldmatrix from ping-pong SMEM tiles each step).
// Warp q owns m-tiles {q, q+4, q+8} => gate rows 16q..16q+15 for r,z,n,
// so each thread's D fragment holds complete (r,z,n) triples for its
// (unit,node) pairs: gates are computed entirely in registers.
// One __syncthreads per step; no mbarriers.
// Head: complete-graph GCN collapses to dense matmuls on per-graph mean h.
// ============================================================================

#define T_LEN 500
#define N_NODES 6144
#define NCTA 128
#define NODES_CTA 48
#define CTA_THREADS 128

typedef uint32_t u32;

__device__ float g_h[N_NODES * 64];

// ---------------- SMEM layout (byte offsets) ----------------
#define SM_W_HI 0                    // 192 rows x 128B (fp16, swz)   24576
#define SM_W_LO 24576                //                               24576
#define SM_H    49152                // 2 buf x 2 split x 48x128B     24576
#define SM_X    73728                // 500 x 48 f32                  96000
#define SMEM_TOTAL 169728

// ---------------- helpers ----------------

__device__ __forceinline__ u32 smem_u32(const void* p) {
    u32 a;
    asm("{ .reg .u64 t; cvta.to.shared.u64 t, %1; cvt.u32.u64 %0, t; }" : "=r"(a) : "l"(p));
    return a;
}
// SW128-style xor swizzle on a (row*128 + kbyte) offset: kbyte ^= (row&7)<<4
__device__ __forceinline__ u32 swz(u32 off) { return off ^ ((off >> 3) & 0x70); }

__device__ __forceinline__ void ldsm_x4(u32* r, u32 addr) {
    asm volatile("ldmatrix.sync.aligned.m8n8.x4.shared.b16 {%0,%1,%2,%3}, [%4];"
        : "=r"(r[0]), "=r"(r[1]), "=r"(r[2]), "=r"(r[3]) : "r"(addr));
}
__device__ __forceinline__ void ldsm_x2(u32* r, u32 addr) {
    asm volatile("ldmatrix.sync.aligned.m8n8.x2.shared.b16 {%0,%1}, [%2];"
        : "=r"(r[0]), "=r"(r[1]) : "r"(addr));
}
__device__ __forceinline__ void mma16816(float* d, const u32* a, const u32* b) {
    asm volatile("mma.sync.aligned.m16n8k16.row.col.f32.f16.f16.f32 "
        "{%0,%1,%2,%3}, {%4,%5,%6,%7}, {%8,%9}, {%0,%1,%2,%3};"
        : "+f"(d[0]), "+f"(d[1]), "+f"(d[2]), "+f"(d[3])
        : "r"(a[0]), "r"(a[1]), "r"(a[2]), "r"(a[3]), "r"(b[0]), "r"(b[1]));
}

__device__ __forceinline__ float ex2a(float x) { float r; asm("ex2.approx.f32 %0, %1;" : "=f"(r) : "f"(x)); return r; }
__device__ __forceinline__ float rcpa(float x) { float r; asm("rcp.approx.f32 %0, %1;" : "=f"(r) : "f"(x)); return r; }
__device__ __forceinline__ float sigm(float v) { return rcpa(1.0f + ex2a(v * -1.4426950408889634f)); }
__device__ __forceinline__ float tanh_fast(float v) { return fmaf(2.0f, rcpa(1.0f + ex2a(v * -2.8853900817779268f)), -1.0f); }

// ---------------- GRU kernel ----------------

__global__ void __launch_bounds__(CTA_THREADS, 1)
gru_mma_kernel(const float* __restrict__ x_raw,
               const float* __restrict__ w_ih,
               const float* __restrict__ w_hh,
               const float* __restrict__ b_ih,
               const float* __restrict__ b_hh)
{
    extern __shared__ char sm[];
    const u32 smb = smem_u32(sm);
    const int tid = threadIdx.x;
    const int lane = tid & 31;
    const int q = tid >> 5;                 // warp id 0..3
    const int gn0 = blockIdx.x * NODES_CTA;

    // ---- stage W_hh fp16 splits (192 x 64, 128B rows, swizzled) ----
    for (int i = tid; i < 192 * 64; i += CTA_THREADS) {
        int r = i >> 6, k = i & 63;
        float w = w_hh[i];
        __half hi = __float2half_rn(w);
        __half lo = __float2half_rn(w - __half2float(hi));
        u32 off = swz((u32)(r * 128 + k * 2));
        *(__half*)(sm + SM_W_HI + off) = hi;
        *(__half*)(sm + SM_W_LO + off) = lo;
    }
    // ---- zero h tiles (both buffers, both splits) ----
    for (int i = tid; i < 24576 / 4; i += CTA_THREADS)
        ((u32*)(sm + SM_H))[i] = 0u;
    // ---- stage x transposed: xs[t*48 + n] ----
    {
        float* xs = (float*)(sm + SM_X);
        for (int i = tid; i < NODES_CTA * T_LEN; i += CTA_THREADS) {
            int n = i / T_LEN, tt = i - n * T_LEN;
            xs[tt * NODES_CTA + n] = x_raw[(size_t)(gn0 + n) * T_LEN + tt];
        }
    }
    __syncthreads();

    // ---- preload W fragments (A operand, row-major m16n8k16) ----
    // m-tile i of this warp covers W rows 64*i + 16*q .. +16  (i=0:r, 1:z, 2:n)
    // ldmatrix.x4 lane->matrix: lanes 0-7: (m0-7,k0-7), 8-15: (m8-15,k0-7),
    //                           16-23: (m0-7,k8-15), 24-31: (m8-15,k8-15)
    u32 wa_hi[3][4][4], wa_lo[3][4][4];
    {
        int g = lane >> 3;
        int sub_m = (g & 1) * 8;
        int sub_kb = (g >> 1) * 16;
#pragma unroll
        for (int mt = 0; mt < 3; mt++) {
#pragma unroll
            for (int kc = 0; kc < 4; kc++) {
                int row = 64 * mt + 16 * q + sub_m + (lane & 7);
                u32 off = (u32)row * 128 + (u32)((kc * 32 + sub_kb) ^ ((row & 7) << 4));
                ldsm_x4(wa_hi[mt][kc], smb + SM_W_HI + off);
                ldsm_x4(wa_lo[mt][kc], smb + SM_W_LO + off);
            }
        }
    }

    // ---- per-thread gate constants: units u_a = 16q + lane/4, u_b = u_a+8 ----
    const int u_a = 16 * q + (lane >> 2);
    const int u_b = u_a + 8;
    const float cwr_a = w_ih[u_a],        cwr_b = w_ih[u_b];
    const float cwz_a = w_ih[64 + u_a],   cwz_b = w_ih[64 + u_b];
    const float cwn_a = w_ih[128 + u_a],  cwn_b = w_ih[128 + u_b];
    const float cr_a  = b_ih[u_a] + b_hh[u_a];
    const float cr_b  = b_ih[u_b] + b_hh[u_b];
    const float cz_a  = b_ih[64 + u_a] + b_hh[64 + u_a];
    const float cz_b  = b_ih[64 + u_b] + b_hh[64 + u_b];
    const float cbin_a = b_ih[128 + u_a], cbin_b = b_ih[128 + u_b];
    const float cbhn_a = b_hh[128 + u_a], cbhn_b = b_hh[128 + u_b];

    // ---- h-fragment (B operand) lane addressing ----
    // ldmatrix.x2 lanes 0-7: (n0-7, k0-7), lanes 8-15: (n0-7, k8-15)
    const int l15 = lane & 15;
    const int r7 = l15 & 7;
    const int xorv = r7 << 4;
    u32 ko[4];
#pragma unroll
    for (int kc = 0; kc < 4; kc++)
        ko[kc] = (u32)((kc * 32 + ((l15 >> 3) * 16)) ^ xorv);
    const u32 hrow_off = (u32)r7 * 128;

    // h-write addressing: nodes n_a = nt*8 + 2*(lane&3), n_b = n_a+1
    const int nc = 2 * (lane & 3);
    const float* xs = (const float*)(sm + SM_X);

    float hprev[6][4];
#pragma unroll
    for (int nt = 0; nt < 6; nt++)
#pragma unroll
        for (int i = 0; i < 4; i++) hprev[nt][i] = 0.0f;

#pragma unroll 1
    for (int t = 0; t < T_LEN; t++) {
        const int buf = t & 1;
        const u32 rd_hi = smb + SM_H + (u32)buf * 12288;
        const u32 rd_lo = rd_hi + 6144;
        char* wr_hi = sm + SM_H + (buf ^ 1) * 12288;
        char* wr_lo = wr_hi + 6144;
        const float* xrow = xs + t * NODES_CTA;

#pragma unroll
        for (int nt = 0; nt < 6; nt++) {
            // ---- load h fragments for this node tile ----
            u32 hh[4][2], hl[4][2];
            u32 base = (u32)(nt * 1024) + hrow_off;
#pragma unroll
            for (int kc = 0; kc < 4; kc++) {
                ldsm_x2(hh[kc], rd_hi + base + ko[kc]);
                ldsm_x2(hl[kc], rd_lo + base + ko[kc]);
            }
            // ---- 3-term mma: acc[mt][0..3] ----
            float acc[3][4];
#pragma unroll
            for (int mt = 0; mt < 3; mt++)
#pragma unroll
                for (int i = 0; i < 4; i++) acc[mt][i] = 0.0f;
#pragma unroll
            for (int mt = 0; mt < 3; mt++) {
#pragma unroll
                for (int kc = 0; kc < 4; kc++) {
                    mma16816(acc[mt], wa_hi[mt][kc], hh[kc]);
                    mma16816(acc[mt], wa_hi[mt][kc], hl[kc]);
                    mma16816(acc[mt], wa_lo[mt][kc], hh[kc]);
                }
            }
            // ---- gates (all in registers) ----
            // frag element i: 0:(u_a,n_a) 1:(u_a,n_b) 2:(u_b,n_a) 3:(u_b,n_b)
            const int n_a = nt * 8 + nc;
            const float xva = xrow[n_a];
            const float xvb = xrow[n_a + 1];
#pragma unroll
            for (int i = 0; i < 4; i++) {
                const bool ub = (i >= 2);
                const float x = (i & 1) ? xvb : xva;
                const float cwr = ub ? cwr_b : cwr_a;
                const float cwz = ub ? cwz_b : cwz_a;
                const float cwn = ub ? cwn_b : cwn_a;
                const float cr  = ub ? cr_b  : cr_a;
                const float cz  = ub ? cz_b  : cz_a;
                const float cbin = ub ? cbin_b : cbin_a;
                const float cbhn = ub ? cbhn_b : cbhn_a;

                float rr = sigm(acc[0][i] + fmaf(x, cwr, cr));
                float zz = sigm(acc[1][i] + fmaf(x, cwz, cz));
                float nn = tanh_fast(fmaf(rr, acc[2][i] + cbhn, fmaf(x, cwn, cbin)));
                float hp = hprev[nt][i];
                float hn = fmaf(zz, hp - nn, nn);
                hprev[nt][i] = hn;

                __half hi = __float2half_rn(hn);
                __half lo = __float2half_rn(hn - __half2float(hi));
                int node = n_a + (i & 1);
                int u = ub ? u_b : u_a;
                u32 off = (u32)node * 128 + (u32)((u * 2) ^ ((node & 7) << 4));
                *(__half*)(wr_hi + off) = hi;
                *(__half*)(wr_lo + off) = lo;
            }
        }
        __syncthreads();
    }

    // ---- write final h ----
#pragma unroll
    for (int nt = 0; nt < 6; nt++) {
#pragma unroll
        for (int i = 0; i < 4; i++) {
            int node = nt * 8 + nc + (i & 1);
            int u = (i >= 2) ? u_b : u_a;
            g_h[(size_t)(gn0 + node) * 64 + u] = hprev[nt][i];
        }
    }
}

// ---------------- collapsed GCN head ----------------
// out[g] = relu(relu(hbar @ W1 + b1) @ W2 + b2) @ Wfc + bfc,  hbar = mean_12 h

__global__ void __launch_bounds__(128)
head_kernel(const float* __restrict__ W1, const float* __restrict__ b1,
            const float* __restrict__ W2, const float* __restrict__ b2,
            const float* __restrict__ Wfc, const float* __restrict__ bfc,
            float* __restrict__ out)
{
    __shared__ float hbar[64];
    __shared__ float x1s[128];
    __shared__ float x2s[128];
    int g = blockIdx.x, tid = threadIdx.x;

    if (tid < 64) {
        float s = 0.0f;
#pragma unroll
        for (int l = 0; l < 12; l++)
            s += g_h[(size_t)(g * 12 + l) * 64 + tid];
        hbar[tid] = s * (1.0f / 12.0f);
    }
    __syncthreads();

    float s = b1[tid];
#pragma unroll
    for (int k = 0; k < 64; k++)
        s = fmaf(hbar[k], W1[k * 128 + tid], s);
    x1s[tid] = fmaxf(s, 0.0f);
    __syncthreads();

    float s2 = b2[tid];
#pragma unroll
    for (int k = 0; k < 128; k++)
        s2 = fmaf(x1s[k], W2[k * 128 + tid], s2);
    x2s[tid] = fmaxf(s2, 0.0f);
    __syncthreads();

    if (tid < 5) {
        float o = bfc[tid];
#pragma unroll
        for (int k = 0; k < 128; k++)
            o = fmaf(x2s[k], Wfc[k * 5 + tid], o);
        out[g * 5 + tid] = o;
    }
}

// ---------------- launch ----------------
// metadata order: 0 x_raw, 1 edge_index, 2 batch, 3 w_ih, 4 w_hh, 5 b_ih,
//                 6 b_hh, 7 W1, 8 b1, 9 W2, 10 b2, 11 Wfc, 12 bfc

extern "C" void kernel_launch(void* const* d_in, const int* in_sizes, int n_in,
                              void* d_out, int out_size)
{
    const float* x_raw = (const float*)d_in[0];
    const float* w_ih  = (const float*)d_in[3];
    const float* w_hh  = (const float*)d_in[4];
    const float* b_ih  = (const float*)d_in[5];
    const float* b_hh  = (const float*)d_in[6];
    const float* W1    = (const float*)d_in[7];
    const float* b1    = (const float*)d_in[8];
    const float* W2    = (const float*)d_in[9];
    const float* b2    = (const float*)d_in[10];
    const float* Wfc   = (const float*)d_in[11];
    const float* bfc   = (const float*)d_in[12];
    float* out = (float*)d_out;

    cudaFuncSetAttribute(gru_mma_kernel, cudaFuncAttributeMaxDynamicSharedMemorySize, SMEM_TOTAL);

    gru_mma_kernel<<<NCTA, CTA_THREADS, SMEM_TOTAL>>>(x_raw, w_ih, w_hh, b_ih, b_hh);
    head_kernel<<<512, 128>>>(W1, b1, W2, b2, Wfc, bfc, out);
}

// round 5
// speedup vs baseline: 3.1177x; 1.2337x over previous
#include <cuda_runtime.h>
#include <cuda_fp16.h>
#include <cstdint>

// ============================================================================
// ECGRGNN via warp-level mma.sync (base sm_100; tcgen05 unavailable here).
//
// GRU matvec per step: D[192 gates, 48 nodes] = W_hh[192,64] @ h[48,64]^T,
// m16n8k16 fp16 mma, 3-term precision split (fp32 accum):
//   D = Whi*hhi + Whi*hlo + Wlo*hhi
// A = W_hh (fragments preloaded to registers, step-invariant).
// B = h (ldmatrix from ping-pong SMEM each step).
//
// R5: 8 warps/CTA (2 per SMSP) for latency hiding. Warp-group 0 (warps 0-3)
// owns node tiles 0-2, group 1 owns 3-5; groups are fully independent and
// sync on separate named barriers. m-tile accumulator chains interleaved
// innermost for 3-way ILP. Gates computed entirely in registers.
// ============================================================================

#define T_LEN 500
#define N_NODES 6144
#define NCTA 128
#define NODES_CTA 48
#define CTA_THREADS 256

typedef uint32_t u32;

__device__ float g_h[N_NODES * 64];

// ---------------- SMEM layout (byte offsets) ----------------
#define SM_W_HI 0                    // 192 rows x 128B (fp16, swz)   24576
#define SM_W_LO 24576                //                               24576
#define SM_H    49152                // 2 buf x 2 split x 48x128B     24576
#define SM_X    73728                // 500 x 48 f32                  96000
#define SMEM_TOTAL 169728

// ---------------- helpers ----------------

__device__ __forceinline__ u32 smem_u32(const void* p) {
    u32 a;
    asm("{ .reg .u64 t; cvta.to.shared.u64 t, %1; cvt.u32.u64 %0, t; }" : "=r"(a) : "l"(p));
    return a;
}
__device__ __forceinline__ u32 swz(u32 off) { return off ^ ((off >> 3) & 0x70); }

__device__ __forceinline__ void ldsm_x4(u32* r, u32 addr) {
    asm volatile("ldmatrix.sync.aligned.m8n8.x4.shared.b16 {%0,%1,%2,%3}, [%4];"
        : "=r"(r[0]), "=r"(r[1]), "=r"(r[2]), "=r"(r[3]) : "r"(addr));
}
__device__ __forceinline__ void ldsm_x2(u32* r, u32 addr) {
    asm volatile("ldmatrix.sync.aligned.m8n8.x2.shared.b16 {%0,%1}, [%2];"
        : "=r"(r[0]), "=r"(r[1]) : "r"(addr));
}
__device__ __forceinline__ void mma16816(float* d, const u32* a, const u32* b) {
    asm volatile("mma.sync.aligned.m16n8k16.row.col.f32.f16.f16.f32 "
        "{%0,%1,%2,%3}, {%4,%5,%6,%7}, {%8,%9}, {%0,%1,%2,%3};"
        : "+f"(d[0]), "+f"(d[1]), "+f"(d[2]), "+f"(d[3])
        : "r"(a[0]), "r"(a[1]), "r"(a[2]), "r"(a[3]), "r"(b[0]), "r"(b[1]));
}

__device__ __forceinline__ float ex2a(float x) { float r; asm("ex2.approx.f32 %0, %1;" : "=f"(r) : "f"(x)); return r; }
__device__ __forceinline__ float rcpa(float x) { float r; asm("rcp.approx.f32 %0, %1;" : "=f"(r) : "f"(x)); return r; }
__device__ __forceinline__ float sigm(float v) { return rcpa(1.0f + ex2a(v * -1.4426950408889634f)); }
__device__ __forceinline__ float tanh_fast(float v) { return fmaf(2.0f, rcpa(1.0f + ex2a(v * -2.8853900817779268f)), -1.0f); }

// ---------------- GRU kernel ----------------

__global__ void __launch_bounds__(CTA_THREADS, 1)
gru_mma_kernel(const float* __restrict__ x_raw,
               const float* __restrict__ w_ih,
               const float* __restrict__ w_hh,
               const float* __restrict__ b_ih,
               const float* __restrict__ b_hh)
{
    extern __shared__ char sm[];
    const u32 smb = smem_u32(sm);
    const int tid = threadIdx.x;
    const int lane = tid & 31;
    const int wid = tid >> 5;
    const int q = wid & 3;                  // m-tile selector (gate-row block)
    const int grp = wid >> 2;               // warp group: 0 -> nt 0-2, 1 -> nt 3-5
    const int nt0 = grp * 3;
    const int bar_id = 1 + grp;
    const int gn0 = blockIdx.x * NODES_CTA;

    // ---- stage W_hh fp16 splits (192 x 64, 128B rows, swizzled) ----
    for (int i = tid; i < 192 * 64; i += CTA_THREADS) {
        int r = i >> 6, k = i & 63;
        float w = w_hh[i];
        __half hi = __float2half_rn(w);
        __half lo = __float2half_rn(w - __half2float(hi));
        u32 off = swz((u32)(r * 128 + k * 2));
        *(__half*)(sm + SM_W_HI + off) = hi;
        *(__half*)(sm + SM_W_LO + off) = lo;
    }
    // ---- zero h tiles (both buffers, both splits) ----
    for (int i = tid; i < 24576 / 4; i += CTA_THREADS)
        ((u32*)(sm + SM_H))[i] = 0u;
    // ---- stage x transposed: xs[t*48 + n] ----
    {
        float* xs = (float*)(sm + SM_X);
        for (int i = tid; i < NODES_CTA * T_LEN; i += CTA_THREADS) {
            int n = i / T_LEN, tt = i - n * T_LEN;
            xs[tt * NODES_CTA + n] = x_raw[(size_t)(gn0 + n) * T_LEN + tt];
        }
    }
    __syncthreads();

    // ---- preload W fragments (A operand, row-major m16n8k16) ----
    u32 wa_hi[3][4][4], wa_lo[3][4][4];
    {
        int g = lane >> 3;
        int sub_m = (g & 1) * 8;
        int sub_kb = (g >> 1) * 16;
#pragma unroll
        for (int mt = 0; mt < 3; mt++) {
#pragma unroll
            for (int kc = 0; kc < 4; kc++) {
                int row = 64 * mt + 16 * q + sub_m + (lane & 7);
                u32 off = (u32)row * 128 + (u32)((kc * 32 + sub_kb) ^ ((row & 7) << 4));
                ldsm_x4(wa_hi[mt][kc], smb + SM_W_HI + off);
                ldsm_x4(wa_lo[mt][kc], smb + SM_W_LO + off);
            }
        }
    }

    // ---- per-thread gate constants: units u_a = 16q + lane/4, u_b = u_a+8 ----
    const int u_a = 16 * q + (lane >> 2);
    const int u_b = u_a + 8;
    const float cwr_a = w_ih[u_a],        cwr_b = w_ih[u_b];
    const float cwz_a = w_ih[64 + u_a],   cwz_b = w_ih[64 + u_b];
    const float cwn_a = w_ih[128 + u_a],  cwn_b = w_ih[128 + u_b];
    const float cr_a  = b_ih[u_a] + b_hh[u_a];
    const float cr_b  = b_ih[u_b] + b_hh[u_b];
    const float cz_a  = b_ih[64 + u_a] + b_hh[64 + u_a];
    const float cz_b  = b_ih[64 + u_b] + b_hh[64 + u_b];
    const float cbin_a = b_ih[128 + u_a], cbin_b = b_ih[128 + u_b];
    const float cbhn_a = b_hh[128 + u_a], cbhn_b = b_hh[128 + u_b];

    // ---- h-fragment (B operand) lane addressing ----
    const int l15 = lane & 15;
    const int r7 = l15 & 7;
    const int xorv = r7 << 4;
    u32 ko[4];
#pragma unroll
    for (int kc = 0; kc < 4; kc++)
        ko[kc] = (u32)((kc * 32 + ((l15 >> 3) * 16)) ^ xorv);
    const u32 hrow_off = (u32)r7 * 128;

    const int nc = 2 * (lane & 3);
    const float* xs = (const float*)(sm + SM_X);

    float hprev[3][4];
#pragma unroll
    for (int j = 0; j < 3; j++)
#pragma unroll
        for (int i = 0; i < 4; i++) hprev[j][i] = 0.0f;

#pragma unroll 1
    for (int t = 0; t < T_LEN; t++) {
        const int buf = t & 1;
        const u32 rd_hi = smb + SM_H + (u32)buf * 12288;
        const u32 rd_lo = rd_hi + 6144;
        char* wr_hi = sm + SM_H + (buf ^ 1) * 12288;
        char* wr_lo = wr_hi + 6144;
        const float* xrow = xs + t * NODES_CTA;

#pragma unroll
        for (int j = 0; j < 3; j++) {
            const int nt = nt0 + j;
            // ---- load h fragments ----
            u32 hh[4][2], hl[4][2];
            u32 base = (u32)(nt * 1024) + hrow_off;
#pragma unroll
            for (int kc = 0; kc < 4; kc++) {
                ldsm_x2(hh[kc], rd_hi + base + ko[kc]);
                ldsm_x2(hl[kc], rd_lo + base + ko[kc]);
            }
            // ---- 3-term mma, m-tile chains interleaved innermost ----
            float acc[3][4];
#pragma unroll
            for (int mt = 0; mt < 3; mt++)
#pragma unroll
                for (int i = 0; i < 4; i++) acc[mt][i] = 0.0f;
#pragma unroll
            for (int kc = 0; kc < 4; kc++) {
#pragma unroll
                for (int mt = 0; mt < 3; mt++) mma16816(acc[mt], wa_hi[mt][kc], hh[kc]);
#pragma unroll
                for (int mt = 0; mt < 3; mt++) mma16816(acc[mt], wa_hi[mt][kc], hl[kc]);
#pragma unroll
                for (int mt = 0; mt < 3; mt++) mma16816(acc[mt], wa_lo[mt][kc], hh[kc]);
            }
            // ---- gates (registers only) ----
            const int n_a = nt * 8 + nc;
            const float xva = xrow[n_a];
            const float xvb = xrow[n_a + 1];
#pragma unroll
            for (int i = 0; i < 4; i++) {
                const bool ub = (i >= 2);
                const float x = (i & 1) ? xvb : xva;
                const float cwr = ub ? cwr_b : cwr_a;
                const float cwz = ub ? cwz_b : cwz_a;
                const float cwn = ub ? cwn_b : cwn_a;
                const float cr  = ub ? cr_b  : cr_a;
                const float cz  = ub ? cz_b  : cz_a;
                const float cbin = ub ? cbin_b : cbin_a;
                const float cbhn = ub ? cbhn_b : cbhn_a;

                float rr = sigm(acc[0][i] + fmaf(x, cwr, cr));
                float zz = sigm(acc[1][i] + fmaf(x, cwz, cz));
                float nn = tanh_fast(fmaf(rr, acc[2][i] + cbhn, fmaf(x, cwn, cbin)));
                float hp = hprev[j][i];
                float hn = fmaf(zz, hp - nn, nn);
                hprev[j][i] = hn;

                __half hi = __float2half_rn(hn);
                __half lo = __float2half_rn(hn - __half2float(hi));
                int node = n_a + (i & 1);
                int u = ub ? u_b : u_a;
                u32 off = (u32)node * 128 + (u32)((u * 2) ^ ((node & 7) << 4));
                *(__half*)(wr_hi + off) = hi;
                *(__half*)(wr_lo + off) = lo;
            }
        }
        // per-group barrier (groups are independent: disjoint h tiles)
        asm volatile("bar.sync %0, %1;" :: "r"(bar_id), "r"(128) : "memory");
    }

    // ---- write final h ----
#pragma unroll
    for (int j = 0; j < 3; j++) {
#pragma unroll
        for (int i = 0; i < 4; i++) {
            int node = (nt0 + j) * 8 + nc + (i & 1);
            int u = (i >= 2) ? u_b : u_a;
            g_h[(size_t)(gn0 + node) * 64 + u] = hprev[j][i];
        }
    }
}

// ---------------- collapsed GCN head ----------------

__global__ void __launch_bounds__(128)
head_kernel(const float* __restrict__ W1, const float* __restrict__ b1,
            const float* __restrict__ W2, const float* __restrict__ b2,
            const float* __restrict__ Wfc, const float* __restrict__ bfc,
            float* __restrict__ out)
{
    __shared__ float hbar[64];
    __shared__ float x1s[128];
    __shared__ float x2s[128];
    int g = blockIdx.x, tid = threadIdx.x;

    if (tid < 64) {
        float s = 0.0f;
#pragma unroll
        for (int l = 0; l < 12; l++)
            s += g_h[(size_t)(g * 12 + l) * 64 + tid];
        hbar[tid] = s * (1.0f / 12.0f);
    }
    __syncthreads();

    float s = b1[tid];
#pragma unroll
    for (int k = 0; k < 64; k++)
        s = fmaf(hbar[k], W1[k * 128 + tid], s);
    x1s[tid] = fmaxf(s, 0.0f);
    __syncthreads();

    float s2 = b2[tid];
#pragma unroll
    for (int k = 0; k < 128; k++)
        s2 = fmaf(x1s[k], W2[k * 128 + tid], s2);
    x2s[tid] = fmaxf(s2, 0.0f);
    __syncthreads();

    if (tid < 5) {
        float o = bfc[tid];
#pragma unroll
        for (int k = 0; k < 128; k++)
            o = fmaf(x2s[k], Wfc[k * 5 + tid], o);
        out[g * 5 + tid] = o;
    }
}

// ---------------- launch ----------------
// metadata order: 0 x_raw, 1 edge_index, 2 batch, 3 w_ih, 4 w_hh, 5 b_ih,
//                 6 b_hh, 7 W1, 8 b1, 9 W2, 10 b2, 11 Wfc, 12 bfc

extern "C" void kernel_launch(void* const* d_in, const int* in_sizes, int n_in,
                              void* d_out, int out_size)
{
    const float* x_raw = (const float*)d_in[0];
    const float* w_ih  = (const float*)d_in[3];
    const float* w_hh  = (const float*)d_in[4];
    const float* b_ih  = (const float*)d_in[5];
    const float* b_hh  = (const float*)d_in[6];
    const float* W1    = (const float*)d_in[7];
    const float* b1    = (const float*)d_in[8];
    const float* W2    = (const float*)d_in[9];
    const float* b2    = (const float*)d_in[10];
    const float* Wfc   = (const float*)d_in[11];
    const float* bfc   = (const float*)d_in[12];
    float* out = (float*)d_out;

    cudaFuncSetAttribute(gru_mma_kernel, cudaFuncAttributeMaxDynamicSharedMemorySize, SMEM_TOTAL);

    gru_mma_kernel<<<NCTA, CTA_THREADS, SMEM_TOTAL>>>(x_raw, w_ih, w_hh, b_ih, b_hh);
    head_kernel<<<512, 128>>>(W1, b1, W2, b2, Wfc, bfc, out);
}